// round 3
// baseline (speedup 1.0000x reference)
#include <cuda_runtime.h>

#define FRAME_NUMBER 16
#define FRAME_SIZE   128
#define SAMPLE_NUM   16
#define NUM_EVENTS   1048576
#define EV_PER_FRAME (NUM_EVENTS / FRAME_NUMBER)      /* 65536 */
#define BINS         (FRAME_SIZE * FRAME_SIZE)        /* 16384 */

// Scratch: packed bin id (y*128 + x) per event, u16 (bin < 16384). 2 MB.
__device__ unsigned short g_bins[NUM_EVENTS];

// ---------------------------------------------------------------------------
// Prepass: pack (x, y) -> u16 bin, handling int64 OR int32 index dtype.
// Detection: view buffer as int32. If dtype is int64, words [N-1],[N-3],... are
// HIGH words of mid-range sorted t values -> all zero. If int32, those words
// are the tail of the sorted t row (~65535) -> nonzero.
// ---------------------------------------------------------------------------
__global__ __launch_bounds__(256)
void bins_kernel(const int* __restrict__ idx32) {
    const int e = (blockIdx.x * blockDim.x + threadIdx.x) * 4;  // first event
    const bool is64 = (idx32[NUM_EVENTS - 1] == 0) &&
                      (idx32[NUM_EVENTS - 3] == 0) &&
                      (idx32[NUM_EVENTS - 5] == 0) &&
                      (idx32[NUM_EVENTS - 7] == 0);
    int x0, x1, x2, x3, y0, y1, y2, y3;
    if (is64) {
        const longlong2* __restrict__ px =
            reinterpret_cast<const longlong2*>(idx32) + (NUM_EVENTS + e) / 2;
        const longlong2* __restrict__ py =
            reinterpret_cast<const longlong2*>(idx32) + (2 * NUM_EVENTS + e) / 2;
        longlong2 xa = px[0], xb = px[1];
        longlong2 ya = py[0], yb = py[1];
        x0 = (int)xa.x; x1 = (int)xa.y; x2 = (int)xb.x; x3 = (int)xb.y;
        y0 = (int)ya.x; y1 = (int)ya.y; y2 = (int)yb.x; y3 = (int)yb.y;
    } else {
        const int4 x4 = *reinterpret_cast<const int4*>(idx32 + NUM_EVENTS + e);
        const int4 y4 = *reinterpret_cast<const int4*>(idx32 + 2 * NUM_EVENTS + e);
        x0 = x4.x; x1 = x4.y; x2 = x4.z; x3 = x4.w;
        y0 = y4.x; y1 = y4.y; y2 = y4.z; y3 = y4.w;
    }
    ushort4 o;
    o.x = (unsigned short)(y0 * FRAME_SIZE + x0);
    o.y = (unsigned short)(y1 * FRAME_SIZE + x1);
    o.z = (unsigned short)(y2 * FRAME_SIZE + x2);
    o.w = (unsigned short)(y3 * FRAME_SIZE + x3);
    *reinterpret_cast<ushort4*>(g_bins + e) = o;
}

// ---------------------------------------------------------------------------
// Main: one CTA per (frame, sample, channel). 128x128 f32 single-channel
// histogram in smem (64 KB -> 2 CTAs/SM), smem atomics, coalesced writeback.
// Channel c=1 accumulates relu(v), c=0 accumulates relu(-v); an event fires
// in exactly one of the two CTAs (predicated off in the other).
// out[f, s, c, y, x] : flat = ((f*S + s)*2 + c)*16384 + y*128 + x
// ---------------------------------------------------------------------------
#define TPB      1024
#define EV_PER_T 8                         /* events per thread per iter */
#define CHUNK    (TPB * EV_PER_T)          /* 8192 events per iter */
#define NITER    (EV_PER_FRAME / CHUNK)    /* 8 iterations */

__device__ __forceinline__ void scat(float* hist, float v, int bin, float sgn) {
    const float w = fmaxf(v * sgn, 0.0f);
    if (w > 0.0f) atomicAdd(&hist[bin], w);
}

__global__ __launch_bounds__(TPB, 2)
void accum_kernel(const float* __restrict__ vals, float* __restrict__ out) {
    __shared__ float hist[BINS];          // 64 KB
    const int f = blockIdx.x;
    const int s = blockIdx.y;
    const int c = blockIdx.z;             // 0 = neg, 1 = pos
    const float sgn = c ? 1.0f : -1.0f;

    {
        float4 z = make_float4(0.f, 0.f, 0.f, 0.f);
        float4* h4 = reinterpret_cast<float4*>(hist);
        #pragma unroll
        for (int i = threadIdx.x; i < BINS / 4; i += TPB) h4[i] = z;
    }
    __syncthreads();

    const float* __restrict__ v =
        vals + (size_t)s * NUM_EVENTS + (size_t)f * EV_PER_FRAME;
    const unsigned short* __restrict__ b = g_bins + f * EV_PER_FRAME;

    const int t8 = threadIdx.x * EV_PER_T;

    // prologue loads (3 vector loads per chunk of 8 events)
    float4 cv0 = *reinterpret_cast<const float4*>(v + t8);
    float4 cv1 = *reinterpret_cast<const float4*>(v + t8 + 4);
    uint4  cb  = *reinterpret_cast<const uint4*>(b + t8);

    #pragma unroll
    for (int it = 0; it < NITER; ++it) {
        float4 nv0, nv1; uint4 nb;
        if (it + 1 < NITER) {
            const int nidx = (it + 1) * CHUNK + t8;
            nv0 = *reinterpret_cast<const float4*>(v + nidx);
            nv1 = *reinterpret_cast<const float4*>(v + nidx + 4);
            nb  = *reinterpret_cast<const uint4*>(b + nidx);
        }
        scat(hist, cv0.x, (int)(cb.x & 0xFFFFu), sgn);
        scat(hist, cv0.y, (int)(cb.x >> 16),     sgn);
        scat(hist, cv0.z, (int)(cb.y & 0xFFFFu), sgn);
        scat(hist, cv0.w, (int)(cb.y >> 16),     sgn);
        scat(hist, cv1.x, (int)(cb.z & 0xFFFFu), sgn);
        scat(hist, cv1.y, (int)(cb.z >> 16),     sgn);
        scat(hist, cv1.z, (int)(cb.w & 0xFFFFu), sgn);
        scat(hist, cv1.w, (int)(cb.w >> 16),     sgn);
        if (it + 1 < NITER) { cv0 = nv0; cv1 = nv1; cb = nb; }
    }
    __syncthreads();

    float4* __restrict__ o = reinterpret_cast<float4*>(
        out + ((size_t)(f * SAMPLE_NUM + s) * 2 + c) * BINS);
    const float4* h4 = reinterpret_cast<const float4*>(hist);
    #pragma unroll
    for (int i = threadIdx.x; i < BINS / 4; i += TPB) o[i] = h4[i];
}

extern "C" void kernel_launch(void* const* d_in, const int* in_sizes, int n_in,
                              void* d_out, int out_size) {
    (void)in_sizes; (void)n_in; (void)out_size;
    const float* vals  = (const float*)d_in[0];
    const int*   idx32 = (const int*)d_in[1];   // raw view; dtype detected on device
    float*       out   = (float*)d_out;

    bins_kernel<<<NUM_EVENTS / (256 * 4), 256>>>(idx32);
    accum_kernel<<<dim3(FRAME_NUMBER, SAMPLE_NUM, 2), TPB>>>(vals, out);
}

// round 4
// speedup vs baseline: 1.4015x; 1.4015x over previous
#include <cuda_runtime.h>

#define FRAME_NUMBER 16
#define FRAME_SIZE   128
#define SAMPLE_NUM   16
#define NUM_EVENTS   1048576
#define EV_PER_FRAME (NUM_EVENTS / FRAME_NUMBER)      /* 65536 */
#define BINS         (FRAME_SIZE * FRAME_SIZE)        /* 16384 */
#define HIST         (2 * BINS)                       /* 32768 floats = 128 KB */

// Scratch: packed bin id (y*128 + x) per event, u16 (bin < 16384). 2 MB.
__device__ unsigned short g_bins[NUM_EVENTS];

// ---------------------------------------------------------------------------
// Prepass: pack (x, y) -> u16 bin, handling int64 OR int32 index dtype.
// Detection: view buffer as int32. If dtype is int64, words [N-1],[N-3],... are
// HIGH words of mid-range sorted t values -> all zero. If int32, those words
// are the tail of the sorted t row (~65535) -> nonzero.
// ---------------------------------------------------------------------------
__global__ __launch_bounds__(256)
void bins_kernel(const int* __restrict__ idx32) {
    const int e = (blockIdx.x * blockDim.x + threadIdx.x) * 4;  // first event
    const bool is64 = (idx32[NUM_EVENTS - 1] == 0) &&
                      (idx32[NUM_EVENTS - 3] == 0) &&
                      (idx32[NUM_EVENTS - 5] == 0) &&
                      (idx32[NUM_EVENTS - 7] == 0);
    int x0, x1, x2, x3, y0, y1, y2, y3;
    if (is64) {
        const longlong2* __restrict__ px =
            reinterpret_cast<const longlong2*>(idx32) + (NUM_EVENTS + e) / 2;
        const longlong2* __restrict__ py =
            reinterpret_cast<const longlong2*>(idx32) + (2 * NUM_EVENTS + e) / 2;
        longlong2 xa = px[0], xb = px[1];
        longlong2 ya = py[0], yb = py[1];
        x0 = (int)xa.x; x1 = (int)xa.y; x2 = (int)xb.x; x3 = (int)xb.y;
        y0 = (int)ya.x; y1 = (int)ya.y; y2 = (int)yb.x; y3 = (int)yb.y;
    } else {
        const int4 x4 = *reinterpret_cast<const int4*>(idx32 + NUM_EVENTS + e);
        const int4 y4 = *reinterpret_cast<const int4*>(idx32 + 2 * NUM_EVENTS + e);
        x0 = x4.x; x1 = x4.y; x2 = x4.z; x3 = x4.w;
        y0 = y4.x; y1 = y4.y; y2 = y4.z; y3 = y4.w;
    }
    ushort4 o;
    o.x = (unsigned short)(y0 * FRAME_SIZE + x0);
    o.y = (unsigned short)(y1 * FRAME_SIZE + x1);
    o.z = (unsigned short)(y2 * FRAME_SIZE + x2);
    o.w = (unsigned short)(y3 * FRAME_SIZE + x3);
    *reinterpret_cast<ushort4*>(g_bins + e) = o;
}

// ---------------------------------------------------------------------------
// Main: one CTA per (frame, sample). Full 2x128x128 f32 histogram in dynamic
// smem (128 KB), smem atomics, coalesced float4 writeback.
// Depth-4 rotating prefetch: loads run 4 chunks (~2x DRAM latency) ahead of
// the atomics so the ATOMS pipe never waits on long_scoreboard.
// out[f, s, c, y, x] : flat = (f*S + s)*32768 + c*16384 + y*128 + x
// ---------------------------------------------------------------------------
#define TPB      1024
#define EV_PER_T 4                         /* events per thread per chunk */
#define CHUNK    (TPB * EV_PER_T)          /* 4096 events per chunk */
#define NITER    (EV_PER_FRAME / CHUNK)    /* 16 chunks */
#define DEPTH    4                         /* prefetch distance */

__global__ __launch_bounds__(TPB, 1)
void accum_kernel(const float* __restrict__ vals, float* __restrict__ out) {
    extern __shared__ float hist[];   // HIST floats = 128 KB
    const int f = blockIdx.x;
    const int s = blockIdx.y;

    // zero histogram (float4 stores)
    {
        float4 z = make_float4(0.f, 0.f, 0.f, 0.f);
        float4* h4 = reinterpret_cast<float4*>(hist);
        #pragma unroll
        for (int i = threadIdx.x; i < HIST / 4; i += TPB) h4[i] = z;
    }
    __syncthreads();

    const float* __restrict__ v =
        vals + (size_t)s * NUM_EVENTS + (size_t)f * EV_PER_FRAME;
    const unsigned short* __restrict__ b = g_bins + f * EV_PER_FRAME;

    const int t4 = threadIdx.x * EV_PER_T;

    float4 vb[DEPTH];
    uint2  bb[DEPTH];

    // prologue: fill the pipeline DEPTH chunks deep
    #pragma unroll
    for (int d = 0; d < DEPTH; ++d) {
        const int idx = d * CHUNK + t4;
        vb[d] = __ldcs(reinterpret_cast<const float4*>(v + idx));
        bb[d] = *reinterpret_cast<const uint2*>(b + idx);
    }

    #pragma unroll
    for (int it = 0; it < NITER; ++it) {
        const int slot = it % DEPTH;
        const float4 cv = vb[slot];
        const uint2  cb = bb[slot];
        if (it + DEPTH < NITER) {
            const int idx = (it + DEPTH) * CHUNK + t4;
            vb[slot] = __ldcs(reinterpret_cast<const float4*>(v + idx));
            bb[slot] = *reinterpret_cast<const uint2*>(b + idx);
        }
        atomicAdd(&hist[(cv.x > 0.0f ? BINS : 0) + (int)(cb.x & 0xFFFFu)], fabsf(cv.x));
        atomicAdd(&hist[(cv.y > 0.0f ? BINS : 0) + (int)(cb.x >> 16)],     fabsf(cv.y));
        atomicAdd(&hist[(cv.z > 0.0f ? BINS : 0) + (int)(cb.y & 0xFFFFu)], fabsf(cv.z));
        atomicAdd(&hist[(cv.w > 0.0f ? BINS : 0) + (int)(cb.y >> 16)],     fabsf(cv.w));
    }
    __syncthreads();

    // coalesced writeback
    float4* __restrict__ o =
        reinterpret_cast<float4*>(out + (size_t)(f * SAMPLE_NUM + s) * HIST);
    const float4* h4 = reinterpret_cast<const float4*>(hist);
    #pragma unroll
    for (int i = threadIdx.x; i < HIST / 4; i += TPB) o[i] = h4[i];
}

extern "C" void kernel_launch(void* const* d_in, const int* in_sizes, int n_in,
                              void* d_out, int out_size) {
    (void)in_sizes; (void)n_in; (void)out_size;
    const float* vals  = (const float*)d_in[0];
    const int*   idx32 = (const int*)d_in[1];   // raw view; dtype detected on device
    float*       out   = (float*)d_out;

    cudaFuncSetAttribute(accum_kernel,
                         cudaFuncAttributeMaxDynamicSharedMemorySize,
                         HIST * (int)sizeof(float));

    bins_kernel<<<NUM_EVENTS / (256 * 4), 256>>>(idx32);
    accum_kernel<<<dim3(FRAME_NUMBER, SAMPLE_NUM), TPB, HIST * sizeof(float)>>>(vals, out);
}